// round 7
// baseline (speedup 1.0000x reference)
#include <cuda_runtime.h>

// Problem constants (fixed shapes for SoftAgg_8873402434226)
#define Bn 8
#define Nn 65536
#define Dn 512
#define Sn 512

// Scratch (sanctioned by harness: __device__ global arrays)
__device__ float g_denom[Sn * Bn * Dn];
__device__ float g_ynum[Sn * Bn * Dn];
__device__ float g_hy[Sn * Bn * Dn];
__device__ int   g_seg[Nn];     // ix converted to int32, clamped to [0, Sn)
__device__ int   g_is64;        // 1 if ix buffer is int64, else 0

// Tile geometry
#define BM 64      // rows per CTA
#define BN 128     // e-cols per CTA
#define BK 16      // k-chunk
#define ASTR 65    // As row stride (floats)
#define BSTR 130   // Bs row stride (floats)

// ---------------------------------------------------------------------------
// Kernel A: detect ix dtype. Reads only the first 128 int32 words (in-bounds
// for either dtype). If ix is int64 with values in [0,512), every odd word
// (the high half) is 0. For int32 data P(all 64 odd words == 0) ~ (1/512)^64.
// ---------------------------------------------------------------------------
__global__ void detect_k(const int* __restrict__ ixw) {
    if (threadIdx.x == 0 && blockIdx.x == 0) {
        int all_odd_zero = 1;
        for (int i = 1; i < 128; i += 2)
            if (ixw[i] != 0) { all_odd_zero = 0; break; }
        g_is64 = all_odd_zero;
    }
}

// ---------------------------------------------------------------------------
// Kernel B: convert ix -> g_seg (int32, clamped). Safe for either layout:
// int64 path reads 2N words (buffer actually has them), int32 path reads N.
// ---------------------------------------------------------------------------
__global__ void cvt_k(const int* __restrict__ ixw) {
    const int n = blockIdx.x * blockDim.x + threadIdx.x;
    const int is64 = g_is64;
    int v = is64 ? ixw[2 * n] : ixw[n];   // low word == value for 0<=ix<2^31
    g_seg[n] = v & (Sn - 1);              // defensive clamp, ids < 512 by spec
}

// ---------------------------------------------------------------------------
// Kernel 0: zero accumulators (runs every replay)
// ---------------------------------------------------------------------------
__global__ void zero_k() {
    int i = blockIdx.x * blockDim.x + threadIdx.x;
    g_denom[i] = 0.0f;
    g_ynum[i]  = 0.0f;
}

// ---------------------------------------------------------------------------
// Kernel 1: fused  g = x*Wg^T + bg,  f = x*Wf^T + bf,  e = exp(g),
//   scalar atomicAdd: denom[s,b,e] += e;  ynum[s,b,e] += f*e
// Grid: (4 e-chunks, B*N/64 row-tiles), 256 threads. All scalar accesses.
// ---------------------------------------------------------------------------
__global__ __launch_bounds__(256, 2)
void main_k(const float* __restrict__ x,
            const float* __restrict__ Wf, const float* __restrict__ bf,
            const float* __restrict__ Wg, const float* __restrict__ bg)
{
    __shared__ float As[BK * ASTR];     // x tile  [k][m]
    __shared__ float Bg[BK * BSTR];     // Wg tile [k][n]
    __shared__ float Bf[BK * BSTR];     // Wf tile [k][n]

    const int tid  = threadIdx.x;
    const int ec   = blockIdx.x;             // e-chunk 0..3
    const int row0 = blockIdx.y * BM;        // flattened row (b*N + n)
    const int b    = row0 >> 16;             // tile never crosses b (N % 64 == 0)
    const int e0   = ec * BN;

    const int tx = tid & 15;                 // col group
    const int ty = tid >> 4;                 // row group
    const int kl = tid & 15;                 // staging k
    const int ml = tid >> 4;                 // staging row/col base

    float ag[4][8], af[4][8];
    #pragma unroll
    for (int i = 0; i < 4; i++)
        #pragma unroll
        for (int j = 0; j < 8; j++) { ag[i][j] = 0.0f; af[i][j] = 0.0f; }

    for (int kc = 0; kc < Dn; kc += BK) {
        #pragma unroll
        for (int it = 0; it < 4; it++) {
            int m = ml + it * 16;
            As[kl * ASTR + m] = x[(size_t)(row0 + m) * Dn + kc + kl];
        }
        #pragma unroll
        for (int it = 0; it < 8; it++) {
            int n = ml + it * 16;
            size_t wo = (size_t)(e0 + n) * Dn + kc + kl;
            Bg[kl * BSTR + n] = Wg[wo];
            Bf[kl * BSTR + n] = Wf[wo];
        }
        __syncthreads();

        #pragma unroll
        for (int k = 0; k < BK; k++) {
            float a[4];
            #pragma unroll
            for (int i = 0; i < 4; i++)
                a[i] = As[k * ASTR + ty + 16 * i];
            float bgv[8], bfv[8];
            #pragma unroll
            for (int j = 0; j < 8; j++) {
                bgv[j] = Bg[k * BSTR + tx + 16 * j];
                bfv[j] = Bf[k * BSTR + tx + 16 * j];
            }
            #pragma unroll
            for (int i = 0; i < 4; i++)
                #pragma unroll
                for (int j = 0; j < 8; j++) {
                    ag[i][j] += a[i] * bgv[j];
                    af[i][j] += a[i] * bfv[j];
                }
        }
        __syncthreads();
    }

    // epilogue: bias, exp, scalar atomic scatter
    float biasg[8], biasf[8];
    #pragma unroll
    for (int j = 0; j < 8; j++) {
        biasg[j] = bg[e0 + tx + 16 * j];
        biasf[j] = bf[e0 + tx + 16 * j];
    }

    #pragma unroll
    for (int i = 0; i < 4; i++) {
        const int row = row0 + ty + 16 * i;        // b*N + n
        const int n   = row & (Nn - 1);
        const int seg = g_seg[n];
        const int base = ((seg * Bn + b) << 9) + e0;
        #pragma unroll
        for (int j = 0; j < 8; j++) {
            const int o = base + tx + 16 * j;
            float ev = __expf(ag[i][j] + biasg[j]);
            atomicAdd(&g_denom[o], ev);
            atomicAdd(&g_ynum[o], (af[i][j] + biasf[j]) * ev);
        }
    }
}

// ---------------------------------------------------------------------------
// Kernel 2: y = ynum/denom in place (guard absent segments)
// ---------------------------------------------------------------------------
__global__ void div_k() {
    int i = blockIdx.x * blockDim.x + threadIdx.x;
    float d = g_denom[i];
    float a = g_ynum[i];
    g_ynum[i] = (d > 0.0f) ? a / d : 0.0f;
}

// ---------------------------------------------------------------------------
// Kernel 3: hy[r,e] = bh[e] + sum_d y[r,d]*Wh[e,d],  r = s*B+b (4096 rows)
// ---------------------------------------------------------------------------
__global__ __launch_bounds__(256, 2)
void hy_k(const float* __restrict__ Wh, const float* __restrict__ bh)
{
    __shared__ float As[BK * ASTR];
    __shared__ float Bh[BK * BSTR];

    const int tid = threadIdx.x;
    const int ec  = blockIdx.x;
    const int rr0 = blockIdx.y * BM;
    const int e0  = ec * BN;

    const int tx = tid & 15;
    const int ty = tid >> 4;
    const int kl = tid & 15;
    const int ml = tid >> 4;

    float acc[4][8];
    #pragma unroll
    for (int i = 0; i < 4; i++)
        #pragma unroll
        for (int j = 0; j < 8; j++) acc[i][j] = 0.0f;

    for (int kc = 0; kc < Dn; kc += BK) {
        #pragma unroll
        for (int it = 0; it < 4; it++) {
            int m = ml + it * 16;
            As[kl * ASTR + m] = g_ynum[(size_t)(rr0 + m) * Dn + kc + kl];
        }
        #pragma unroll
        for (int it = 0; it < 8; it++) {
            int n = ml + it * 16;
            Bh[kl * BSTR + n] = Wh[(size_t)(e0 + n) * Dn + kc + kl];
        }
        __syncthreads();

        #pragma unroll
        for (int k = 0; k < BK; k++) {
            float a[4];
            #pragma unroll
            for (int i = 0; i < 4; i++)
                a[i] = As[k * ASTR + ty + 16 * i];
            float bhv[8];
            #pragma unroll
            for (int j = 0; j < 8; j++)
                bhv[j] = Bh[k * BSTR + tx + 16 * j];
            #pragma unroll
            for (int i = 0; i < 4; i++)
                #pragma unroll
                for (int j = 0; j < 8; j++)
                    acc[i][j] += a[i] * bhv[j];
        }
        __syncthreads();
    }

    #pragma unroll
    for (int i = 0; i < 4; i++) {
        const int r = rr0 + ty + 16 * i;
        #pragma unroll
        for (int j = 0; j < 8; j++) {
            const int e = e0 + tx + 16 * j;
            g_hy[(size_t)r * Dn + e] = acc[i][j] + bh[e];
        }
    }
}

// ---------------------------------------------------------------------------
// Kernel 4: out[b,n,e] = hy[seg[n], b, e]   (scalar gather, hy is L2-hot)
// ---------------------------------------------------------------------------
__global__ void gather_k(float* __restrict__ out)
{
    const int idx = blockIdx.x * 256 + threadIdx.x;   // < B*N*D
    const int e  = idx & (Dn - 1);
    const int nb = idx >> 9;            // b*N + n
    const int n  = nb & (Nn - 1);
    const int b  = nb >> 16;
    const int s  = g_seg[n];
    out[idx] = g_hy[((s * Bn + b) << 9) + e];
}

// ---------------------------------------------------------------------------
extern "C" void kernel_launch(void* const* d_in, const int* in_sizes, int n_in,
                              void* d_out, int out_size)
{
    const float* x   = (const float*)d_in[0];
    const int*   ixw = (const int*)d_in[1];     // raw words; dtype detected on device
    const float* Wf  = (const float*)d_in[2];
    const float* bf  = (const float*)d_in[3];
    const float* Wg  = (const float*)d_in[4];
    const float* bg  = (const float*)d_in[5];
    const float* Wh  = (const float*)d_in[6];
    const float* bh  = (const float*)d_in[7];

    // 0) detect ix dtype (int32 vs int64) and materialize int32 segment ids
    detect_k<<<1, 32>>>(ixw);
    cvt_k<<<Nn / 256, 256>>>(ixw);

    // 1) zero accumulators
    zero_k<<<(Sn * Bn * Dn) / 256, 256>>>();

    // 2) fused g/f GEMM + exp + segment atomic accumulation
    main_k<<<dim3(Dn / BN, (Bn * Nn) / BM), 256>>>(x, Wf, bf, Wg, bg);

    // 3) y = ynum/denom
    div_k<<<(Sn * Bn * Dn) / 256, 256>>>();

    // 4) hy = y @ Wh^T + bh   (4096 x 512 x 512)
    hy_k<<<dim3(Dn / BN, (Sn * Bn) / BM), 256>>>(Wh, bh);

    // 5) out = gather(hy, seg)
    gather_k<<<(Bn * Nn * Dn) / 256, 256>>>((float*)d_out);

    (void)in_sizes; (void)n_in; (void)out_size;
}

// round 8
// speedup vs baseline: 1.2445x; 1.2445x over previous
#include <cuda_runtime.h>

// Problem constants (fixed shapes for SoftAgg_8873402434226)
#define Bn 8
#define Nn 65536
#define Dn 512
#define Sn 512

// Scratch (sanctioned by harness: __device__ global arrays)
__device__ float g_denom[Sn * Bn * Dn];
__device__ float g_ynum[Sn * Bn * Dn];
__device__ float g_hy[Sn * Bn * Dn];
__device__ int   g_seg[Nn];     // ix converted to int32, clamped to [0, Sn)
__device__ int   g_is64;        // 1 if ix buffer is int64, else 0

// Tile geometry
#define BM 128     // rows per CTA
#define BE 64      // e-cols per CTA
#define BK 16      // k-chunk
#define ASTR 132   // As row stride (floats), multiple of 4, mod 32 = 4
#define BSTR 68    // B* row stride (floats), multiple of 4, mod 32 = 4

// ---------------------------------------------------------------------------
// Kernel A: detect ix dtype from first 128 words (in-bounds either way).
// int64 with values < 512 -> every odd (high) word is 0.
// ---------------------------------------------------------------------------
__global__ void detect_k(const int* __restrict__ ixw) {
    if (threadIdx.x == 0 && blockIdx.x == 0) {
        int all_odd_zero = 1;
        for (int i = 1; i < 128; i += 2)
            if (ixw[i] != 0) { all_odd_zero = 0; break; }
        g_is64 = all_odd_zero;
    }
}

// ---------------------------------------------------------------------------
// Kernel B: ix -> g_seg (int32, clamped to [0,512))
// ---------------------------------------------------------------------------
__global__ void cvt_k(const int* __restrict__ ixw) {
    const int n = blockIdx.x * blockDim.x + threadIdx.x;
    const int is64 = g_is64;
    int v = is64 ? ixw[2 * n] : ixw[n];
    g_seg[n] = v & (Sn - 1);
}

// ---------------------------------------------------------------------------
// Kernel 0: zero accumulators (float4)
// ---------------------------------------------------------------------------
__global__ void zero_k() {
    int i = blockIdx.x * blockDim.x + threadIdx.x;
    float4 z = make_float4(0.f, 0.f, 0.f, 0.f);
    ((float4*)g_denom)[i] = z;
    ((float4*)g_ynum)[i]  = z;
}

// ---------------------------------------------------------------------------
// Kernel 1: fused dual GEMM  g = x*Wg^T + bg, f = x*Wf^T + bf, e = exp(g),
//   atomicAdd denom[s,b,e] += e;  ynum[s,b,e] += f*e
// CTA tile: 128 rows x 64 e. 256 threads, micro-tile 8 rows x 4 e x {g,f}.
// Grid: (8 e-chunks fastest, B*N/128 row-tiles) -> x tile L2-shared.
// ---------------------------------------------------------------------------
__global__ __launch_bounds__(256, 2)
void main_k(const float* __restrict__ x,
            const float* __restrict__ Wf, const float* __restrict__ bf,
            const float* __restrict__ Wg, const float* __restrict__ bg)
{
    __shared__ float As[BK * ASTR];   // x tile  [k][m]
    __shared__ float Bg[BK * BSTR];   // Wg tile [k][e]
    __shared__ float Bf[BK * BSTR];   // Wf tile [k][e]

    const int tid  = threadIdx.x;
    const int ec   = blockIdx.x;           // e-chunk 0..7
    const int row0 = blockIdx.y * BM;      // flattened row (b*N + n)
    const int b    = row0 >> 16;           // tile never crosses b
    const int e0   = ec * BE;

    const int tx = tid & 15;               // e group: cols e0 + tx*4 .. +3
    const int ty = tid >> 4;               // row group: rows ty*8 .. +7
    const int m0 = ty * 8;

    // staging coords
    const int srow = tid & 127;            // As: row this thread stages
    const int sh   = tid >> 7;             // 0/1: which pair of float4 chunks
    const int we   = tid >> 2;             // B*: e this thread stages
    const int wc   = tid & 3;              // B*: which float4 chunk

    float ag[8][4], af[8][4];
    #pragma unroll
    for (int i = 0; i < 8; i++)
        #pragma unroll
        for (int j = 0; j < 4; j++) { ag[i][j] = 0.f; af[i][j] = 0.f; }

    const float4* x4  = (const float4*)x;
    const float4* wg4 = (const float4*)Wg;
    const float4* wf4 = (const float4*)Wf;

    for (int kc = 0; kc < Dn; kc += BK) {
        const int kq = kc >> 2;  // k-chunk in float4 units
        // stage As[k][m] = x[row0+m][kc+k]  (transpose via scalar STS, conflict-free)
        #pragma unroll
        for (int it = 0; it < 2; it++) {
            int cc = sh * 2 + it;          // 0..3
            float4 v = x4[(size_t)(row0 + srow) * (Dn / 4) + kq + cc];
            As[(cc * 4 + 0) * ASTR + srow] = v.x;
            As[(cc * 4 + 1) * ASTR + srow] = v.y;
            As[(cc * 4 + 2) * ASTR + srow] = v.z;
            As[(cc * 4 + 3) * ASTR + srow] = v.w;
        }
        // stage Bg/Bf[k][e] = W[e0+e][kc+k]
        {
            float4 gv = wg4[(size_t)(e0 + we) * (Dn / 4) + kq + wc];
            float4 fv = wf4[(size_t)(e0 + we) * (Dn / 4) + kq + wc];
            Bg[(wc * 4 + 0) * BSTR + we] = gv.x;
            Bg[(wc * 4 + 1) * BSTR + we] = gv.y;
            Bg[(wc * 4 + 2) * BSTR + we] = gv.z;
            Bg[(wc * 4 + 3) * BSTR + we] = gv.w;
            Bf[(wc * 4 + 0) * BSTR + we] = fv.x;
            Bf[(wc * 4 + 1) * BSTR + we] = fv.y;
            Bf[(wc * 4 + 2) * BSTR + we] = fv.z;
            Bf[(wc * 4 + 3) * BSTR + we] = fv.w;
        }
        __syncthreads();

        #pragma unroll
        for (int k = 0; k < BK; k++) {
            float4 a0 = *(const float4*)(As + k * ASTR + m0);
            float4 a1 = *(const float4*)(As + k * ASTR + m0 + 4);
            float4 bgv = *(const float4*)(Bg + k * BSTR + tx * 4);
            float4 bfv = *(const float4*)(Bf + k * BSTR + tx * 4);
            float a[8] = {a0.x, a0.y, a0.z, a0.w, a1.x, a1.y, a1.z, a1.w};
            float gvv[4] = {bgv.x, bgv.y, bgv.z, bgv.w};
            float fvv[4] = {bfv.x, bfv.y, bfv.z, bfv.w};
            #pragma unroll
            for (int i = 0; i < 8; i++) {
                #pragma unroll
                for (int j = 0; j < 4; j++) {
                    ag[i][j] += a[i] * gvv[j];
                    af[i][j] += a[i] * fvv[j];
                }
            }
        }
        __syncthreads();
    }

    // epilogue: bias, exp, atomic scatter
    const int ecol = e0 + tx * 4;
    float biasg[4], biasf[4];
    #pragma unroll
    for (int j = 0; j < 4; j++) { biasg[j] = bg[ecol + j]; biasf[j] = bf[ecol + j]; }

    #pragma unroll
    for (int i = 0; i < 8; i++) {
        const int row = row0 + m0 + i;
        const int n   = row & (Nn - 1);
        const int seg = g_seg[n];
        const int base = ((seg * Bn + b) << 9) + ecol;
        #pragma unroll
        for (int j = 0; j < 4; j++) {
            float ev = __expf(ag[i][j] + biasg[j]);
            atomicAdd(&g_denom[base + j], ev);
            atomicAdd(&g_ynum[base + j], (af[i][j] + biasf[j]) * ev);
        }
    }
}

// ---------------------------------------------------------------------------
// Kernel 2: y = ynum/denom in place (float4)
// ---------------------------------------------------------------------------
__global__ void div_k() {
    int i = blockIdx.x * blockDim.x + threadIdx.x;
    float4 d = ((const float4*)g_denom)[i];
    float4 a = ((const float4*)g_ynum)[i];
    float4 r;
    r.x = (d.x > 0.f) ? a.x / d.x : 0.f;
    r.y = (d.y > 0.f) ? a.y / d.y : 0.f;
    r.z = (d.z > 0.f) ? a.z / d.z : 0.f;
    r.w = (d.w > 0.f) ? a.w / d.w : 0.f;
    ((float4*)g_ynum)[i] = r;
}

// ---------------------------------------------------------------------------
// Kernel 3: hy[r,e] = bh[e] + sum_d y[r,d]*Wh[e,d],  r = s*B+b (4096 rows)
// Same vectorized tiling, single matrix, plain store.
// ---------------------------------------------------------------------------
__global__ __launch_bounds__(256, 2)
void hy_k(const float* __restrict__ Wh, const float* __restrict__ bh)
{
    __shared__ float As[BK * ASTR];
    __shared__ float Bh[BK * BSTR];

    const int tid = threadIdx.x;
    const int ec  = blockIdx.x;
    const int rr0 = blockIdx.y * BM;
    const int e0  = ec * BE;

    const int tx = tid & 15;
    const int ty = tid >> 4;
    const int m0 = ty * 8;

    const int srow = tid & 127;
    const int sh   = tid >> 7;
    const int we   = tid >> 2;
    const int wc   = tid & 3;

    float acc[8][4];
    #pragma unroll
    for (int i = 0; i < 8; i++)
        #pragma unroll
        for (int j = 0; j < 4; j++) acc[i][j] = 0.f;

    const float4* y4  = (const float4*)g_ynum;
    const float4* wh4 = (const float4*)Wh;

    for (int kc = 0; kc < Dn; kc += BK) {
        const int kq = kc >> 2;
        #pragma unroll
        for (int it = 0; it < 2; it++) {
            int cc = sh * 2 + it;
            float4 v = y4[(size_t)(rr0 + srow) * (Dn / 4) + kq + cc];
            As[(cc * 4 + 0) * ASTR + srow] = v.x;
            As[(cc * 4 + 1) * ASTR + srow] = v.y;
            As[(cc * 4 + 2) * ASTR + srow] = v.z;
            As[(cc * 4 + 3) * ASTR + srow] = v.w;
        }
        {
            float4 hv = wh4[(size_t)(e0 + we) * (Dn / 4) + kq + wc];
            Bh[(wc * 4 + 0) * BSTR + we] = hv.x;
            Bh[(wc * 4 + 1) * BSTR + we] = hv.y;
            Bh[(wc * 4 + 2) * BSTR + we] = hv.z;
            Bh[(wc * 4 + 3) * BSTR + we] = hv.w;
        }
        __syncthreads();

        #pragma unroll
        for (int k = 0; k < BK; k++) {
            float4 a0 = *(const float4*)(As + k * ASTR + m0);
            float4 a1 = *(const float4*)(As + k * ASTR + m0 + 4);
            float4 bv = *(const float4*)(Bh + k * BSTR + tx * 4);
            float a[8] = {a0.x, a0.y, a0.z, a0.w, a1.x, a1.y, a1.z, a1.w};
            float hvv[4] = {bv.x, bv.y, bv.z, bv.w};
            #pragma unroll
            for (int i = 0; i < 8; i++)
                #pragma unroll
                for (int j = 0; j < 4; j++)
                    acc[i][j] += a[i] * hvv[j];
        }
        __syncthreads();
    }

    const int ecol = e0 + tx * 4;
    float4 bv;
    bv.x = bh[ecol]; bv.y = bh[ecol + 1]; bv.z = bh[ecol + 2]; bv.w = bh[ecol + 3];

    #pragma unroll
    for (int i = 0; i < 8; i++) {
        float4 v;
        v.x = acc[i][0] + bv.x;
        v.y = acc[i][1] + bv.y;
        v.z = acc[i][2] + bv.z;
        v.w = acc[i][3] + bv.w;
        *(float4*)(g_hy + (size_t)(rr0 + m0 + i) * Dn + ecol) = v;
    }
}

// ---------------------------------------------------------------------------
// Kernel 4: out[b,n,e] = hy[seg[n], b, e]   (float4 gather, hy L2-hot)
// ---------------------------------------------------------------------------
__global__ void gather_k(float4* __restrict__ out)
{
    const int idx = blockIdx.x * 256 + threadIdx.x;   // < B*N*128
    const int e4 = idx & 127;
    const int nb = idx >> 7;            // b*N + n
    const int n  = nb & (Nn - 1);
    const int b  = nb >> 16;
    const int s  = g_seg[n];
    out[idx] = ((const float4*)g_hy)[((s * Bn + b) << 7) + e4];
}

// ---------------------------------------------------------------------------
extern "C" void kernel_launch(void* const* d_in, const int* in_sizes, int n_in,
                              void* d_out, int out_size)
{
    const float* x   = (const float*)d_in[0];
    const int*   ixw = (const int*)d_in[1];
    const float* Wf  = (const float*)d_in[2];
    const float* bf  = (const float*)d_in[3];
    const float* Wg  = (const float*)d_in[4];
    const float* bg  = (const float*)d_in[5];
    const float* Wh  = (const float*)d_in[6];
    const float* bh  = (const float*)d_in[7];

    // 0) seg ids
    detect_k<<<1, 32>>>(ixw);
    cvt_k<<<Nn / 256, 256>>>(ixw);

    // 1) zero accumulators (float4 elems)
    zero_k<<<(Sn * Bn * Dn / 4) / 256, 256>>>();

    // 2) fused g/f GEMM + exp + segment atomic accumulation
    main_k<<<dim3(Dn / BE, (Bn * Nn) / BM), 256>>>(x, Wf, bf, Wg, bg);

    // 3) y = ynum/denom (float4 elems)
    div_k<<<(Sn * Bn * Dn / 4) / 256, 256>>>();

    // 4) hy = y @ Wh^T + bh   (4096 x 512 x 512)
    hy_k<<<dim3(Dn / BE, (Sn * Bn) / BM), 256>>>(Wh, bh);

    // 5) out = gather(hy, seg)  (float4 elems)
    gather_k<<<(Bn * Nn * 128) / 256, 256>>>((float4*)d_out);

    (void)in_sizes; (void)n_in; (void)out_size;
}

// round 9
// speedup vs baseline: 1.4095x; 1.1326x over previous
#include <cuda_runtime.h>

// Problem constants (fixed shapes for SoftAgg_8873402434226)
#define Bn 8
#define Nn 65536
#define Dn 512
#define Sn 512

// Scratch (sanctioned by harness: __device__ global arrays)
__device__ float g_denom[Sn * Bn * Dn];
__device__ float g_ynum[Sn * Bn * Dn];
__device__ float g_hy[Sn * Bn * Dn];
__device__ int   g_seg[Nn];     // ix as int32, clamped to [0, Sn)
__device__ int   g_is64;        // 1 if ix buffer is int64

// main_k tile geometry
#define BM 128     // rows per CTA
#define BE 64      // e-cols per CTA
#define KC 32      // k per smem stage
#define ASTR 136   // As row stride: (8*lq + lr) % 32 bijective -> conflict-free frags
#define BSTR 72    // Bs row stride: same property (72 % 32 == 8)

// hy_k tile geometry (fp32 SIMT, kernel is tiny)
#define HASTR 132
#define HBSTR 68

// ---------------------------------------------------------------------------
__global__ void detect_k(const int* __restrict__ ixw) {
    if (threadIdx.x == 0 && blockIdx.x == 0) {
        int all_odd_zero = 1;
        for (int i = 1; i < 128; i += 2)
            if (ixw[i] != 0) { all_odd_zero = 0; break; }
        g_is64 = all_odd_zero;
    }
}

__global__ void cvt_k(const int* __restrict__ ixw) {
    const int n = blockIdx.x * blockDim.x + threadIdx.x;
    const int is64 = g_is64;
    int v = is64 ? ixw[2 * n] : ixw[n];
    g_seg[n] = v & (Sn - 1);
}

__global__ void zero_k() {
    int i = blockIdx.x * blockDim.x + threadIdx.x;
    float4 z = make_float4(0.f, 0.f, 0.f, 0.f);
    ((float4*)g_denom)[i] = z;
    ((float4*)g_ynum)[i]  = z;
}

// ---------------------------------------------------------------------------
// tf32 helpers
// ---------------------------------------------------------------------------
__device__ __forceinline__ float f2tf32(float f) {
    unsigned o;
    asm("cvt.rna.tf32.f32 %0, %1;" : "=r"(o) : "f"(f));
    return __uint_as_float(o);
}

__device__ __forceinline__ void mma_tf32(float* c, const unsigned* a, const unsigned* b) {
    asm volatile(
        "mma.sync.aligned.m16n8k8.row.col.f32.tf32.tf32.f32 "
        "{%0,%1,%2,%3}, {%4,%5,%6,%7}, {%8,%9}, {%0,%1,%2,%3};"
        : "+f"(c[0]), "+f"(c[1]), "+f"(c[2]), "+f"(c[3])
        : "r"(a[0]), "r"(a[1]), "r"(a[2]), "r"(a[3]), "r"(b[0]), "r"(b[1]));
}

// ---------------------------------------------------------------------------
// Kernel 1: fused dual GEMM via mma.sync tf32.
//   g = x*Wg^T + bg, f = x*Wf^T + bf, e = exp(g)
//   atomicAdd denom[s,b,e] += e;  ynum[s,b,e] += f*e
// CTA 128 rows x 64 e; 8 warps as 4(m) x 2(e); warp tile 32x32.
// Grid: (8 e-chunks fastest, B*N/128 row-tiles).
// ---------------------------------------------------------------------------
__global__ __launch_bounds__(256, 2)
void main_k(const float* __restrict__ x,
            const float* __restrict__ Wf, const float* __restrict__ bf,
            const float* __restrict__ Wg, const float* __restrict__ bg)
{
    __shared__ float As[KC * ASTR];    // [k][m]  17408 B
    __shared__ float Bgs[KC * BSTR];   // [k][e]   9216 B
    __shared__ float Bfs[KC * BSTR];   // [k][e]   9216 B

    const int tid   = threadIdx.x;
    const int ec    = blockIdx.x;
    const int row0  = blockIdx.y * BM;
    const int b     = row0 >> 16;          // tile never crosses b
    const int nbase = row0 & (Nn - 1);
    const int e0    = ec * BE;

    const int lane = tid & 31, w = tid >> 5;
    const int lr = lane >> 2, lq = lane & 3;
    const int m0w = (w & 3) * 32;
    const int e0w = (w >> 2) * 32;

    // staging coords: 4 rows x 128B per warp, fully coalesced
    const int sr = tid >> 3;               // 0..31
    const int sc = tid & 7;                // float4 chunk within 32-k row

    float cg[2][4][4], cf[2][4][4];
    #pragma unroll
    for (int mt = 0; mt < 2; mt++)
        #pragma unroll
        for (int nt = 0; nt < 4; nt++)
            #pragma unroll
            for (int r = 0; r < 4; r++) { cg[mt][nt][r] = 0.f; cf[mt][nt][r] = 0.f; }

    const float4* x4  = (const float4*)x;
    const float4* wg4 = (const float4*)Wg;
    const float4* wf4 = (const float4*)Wf;

    for (int kc = 0; kc < Dn; kc += KC) {
        const int kq = kc >> 2;
        // stage As[k][m] = tf32(x[row0+m][kc+k]): 4 passes x 32 rows
        #pragma unroll
        for (int p = 0; p < 4; p++) {
            int m = p * 32 + sr;
            float4 v = x4[(size_t)(row0 + m) * (Dn / 4) + kq + sc];
            As[(sc * 4 + 0) * ASTR + m] = f2tf32(v.x);
            As[(sc * 4 + 1) * ASTR + m] = f2tf32(v.y);
            As[(sc * 4 + 2) * ASTR + m] = f2tf32(v.z);
            As[(sc * 4 + 3) * ASTR + m] = f2tf32(v.w);
        }
        // stage Bg/Bf[k][e] = tf32(W[e0+e][kc+k]): 2 passes x 32 e
        #pragma unroll
        for (int p = 0; p < 2; p++) {
            int e = p * 32 + sr;
            float4 gv = wg4[(size_t)(e0 + e) * (Dn / 4) + kq + sc];
            float4 fv = wf4[(size_t)(e0 + e) * (Dn / 4) + kq + sc];
            Bgs[(sc * 4 + 0) * BSTR + e] = f2tf32(gv.x);
            Bgs[(sc * 4 + 1) * BSTR + e] = f2tf32(gv.y);
            Bgs[(sc * 4 + 2) * BSTR + e] = f2tf32(gv.z);
            Bgs[(sc * 4 + 3) * BSTR + e] = f2tf32(gv.w);
            Bfs[(sc * 4 + 0) * BSTR + e] = f2tf32(fv.x);
            Bfs[(sc * 4 + 1) * BSTR + e] = f2tf32(fv.y);
            Bfs[(sc * 4 + 2) * BSTR + e] = f2tf32(fv.z);
            Bfs[(sc * 4 + 3) * BSTR + e] = f2tf32(fv.w);
        }
        __syncthreads();

        #pragma unroll
        for (int k8 = 0; k8 < KC / 8; k8++) {
            const int k0 = k8 * 8;
            unsigned a[2][4];
            #pragma unroll
            for (int mt = 0; mt < 2; mt++) {
                const float* ap = As + (k0 + lq) * ASTR + m0w + mt * 16 + lr;
                a[mt][0] = __float_as_uint(ap[0]);
                a[mt][1] = __float_as_uint(ap[8]);
                a[mt][2] = __float_as_uint(ap[4 * ASTR]);
                a[mt][3] = __float_as_uint(ap[4 * ASTR + 8]);
            }
            unsigned bgf[4][2], bff[4][2];
            #pragma unroll
            for (int nt = 0; nt < 4; nt++) {
                const float* gp = Bgs + (k0 + lq) * BSTR + e0w + nt * 8 + lr;
                const float* fp = Bfs + (k0 + lq) * BSTR + e0w + nt * 8 + lr;
                bgf[nt][0] = __float_as_uint(gp[0]);
                bgf[nt][1] = __float_as_uint(gp[4 * BSTR]);
                bff[nt][0] = __float_as_uint(fp[0]);
                bff[nt][1] = __float_as_uint(fp[4 * BSTR]);
            }
            #pragma unroll
            for (int mt = 0; mt < 2; mt++)
                #pragma unroll
                for (int nt = 0; nt < 4; nt++) {
                    mma_tf32(cg[mt][nt], a[mt], bgf[nt]);
                    mma_tf32(cf[mt][nt], a[mt], bff[nt]);
                }
        }
        __syncthreads();
    }

    // epilogue: bias, exp, atomic scatter
    int segs[4];
    #pragma unroll
    for (int mt = 0; mt < 2; mt++)
        #pragma unroll
        for (int h = 0; h < 2; h++)
            segs[mt * 2 + h] = g_seg[nbase + m0w + mt * 16 + h * 8 + lr];

    #pragma unroll
    for (int nt = 0; nt < 4; nt++) {
        const int col = e0 + e0w + nt * 8 + 2 * lq;     // global e column
        const float bg0 = bg[col], bg1 = bg[col + 1];
        const float bf0 = bf[col], bf1 = bf[col + 1];
        #pragma unroll
        for (int mt = 0; mt < 2; mt++) {
            #pragma unroll
            for (int h = 0; h < 2; h++) {
                const int base = ((segs[mt * 2 + h] * Bn + b) << 9) + col;
                float ev0 = __expf(cg[mt][nt][h * 2 + 0] + bg0);
                float ev1 = __expf(cg[mt][nt][h * 2 + 1] + bg1);
                atomicAdd(&g_denom[base + 0], ev0);
                atomicAdd(&g_ynum[base + 0], (cf[mt][nt][h * 2 + 0] + bf0) * ev0);
                atomicAdd(&g_denom[base + 1], ev1);
                atomicAdd(&g_ynum[base + 1], (cf[mt][nt][h * 2 + 1] + bf1) * ev1);
            }
        }
    }
}

// ---------------------------------------------------------------------------
// Kernel 2: y = ynum/denom in place (float4)
// ---------------------------------------------------------------------------
__global__ void div_k() {
    int i = blockIdx.x * blockDim.x + threadIdx.x;
    float4 d = ((const float4*)g_denom)[i];
    float4 a = ((const float4*)g_ynum)[i];
    float4 r;
    r.x = (d.x > 0.f) ? a.x / d.x : 0.f;
    r.y = (d.y > 0.f) ? a.y / d.y : 0.f;
    r.z = (d.z > 0.f) ? a.z / d.z : 0.f;
    r.w = (d.w > 0.f) ? a.w / d.w : 0.f;
    ((float4*)g_ynum)[i] = r;
}

// ---------------------------------------------------------------------------
// Kernel 3: hy[r,e] = bh[e] + sum_d y[r,d]*Wh[e,d]  (4096 rows; fp32 SIMT)
// ---------------------------------------------------------------------------
__global__ __launch_bounds__(256, 2)
void hy_k(const float* __restrict__ Wh, const float* __restrict__ bh)
{
    __shared__ float As[16 * HASTR];
    __shared__ float Bh[16 * HBSTR];

    const int tid = threadIdx.x;
    const int ec  = blockIdx.x;
    const int rr0 = blockIdx.y * BM;
    const int e0  = ec * BE;

    const int tx = tid & 15;
    const int ty = tid >> 4;
    const int m0 = ty * 8;

    const int srow = tid & 127;
    const int sh   = tid >> 7;
    const int we   = tid >> 2;
    const int wc   = tid & 3;

    float acc[8][4];
    #pragma unroll
    for (int i = 0; i < 8; i++)
        #pragma unroll
        for (int j = 0; j < 4; j++) acc[i][j] = 0.f;

    const float4* y4  = (const float4*)g_ynum;
    const float4* wh4 = (const float4*)Wh;

    for (int kc = 0; kc < Dn; kc += 16) {
        const int kq = kc >> 2;
        #pragma unroll
        for (int it = 0; it < 2; it++) {
            int cc = sh * 2 + it;
            float4 v = y4[(size_t)(rr0 + srow) * (Dn / 4) + kq + cc];
            As[(cc * 4 + 0) * HASTR + srow] = v.x;
            As[(cc * 4 + 1) * HASTR + srow] = v.y;
            As[(cc * 4 + 2) * HASTR + srow] = v.z;
            As[(cc * 4 + 3) * HASTR + srow] = v.w;
        }
        {
            float4 hv = wh4[(size_t)(e0 + we) * (Dn / 4) + kq + wc];
            Bh[(wc * 4 + 0) * HBSTR + we] = hv.x;
            Bh[(wc * 4 + 1) * HBSTR + we] = hv.y;
            Bh[(wc * 4 + 2) * HBSTR + we] = hv.z;
            Bh[(wc * 4 + 3) * HBSTR + we] = hv.w;
        }
        __syncthreads();

        #pragma unroll
        for (int k = 0; k < 16; k++) {
            float4 a0 = *(const float4*)(As + k * HASTR + m0);
            float4 a1 = *(const float4*)(As + k * HASTR + m0 + 4);
            float4 bv = *(const float4*)(Bh + k * HBSTR + tx * 4);
            float a[8] = {a0.x, a0.y, a0.z, a0.w, a1.x, a1.y, a1.z, a1.w};
            float hvv[4] = {bv.x, bv.y, bv.z, bv.w};
            #pragma unroll
            for (int i = 0; i < 8; i++)
                #pragma unroll
                for (int j = 0; j < 4; j++)
                    acc[i][j] += a[i] * hvv[j];
        }
        __syncthreads();
    }

    const int ecol = e0 + tx * 4;
    float4 bv;
    bv.x = bh[ecol]; bv.y = bh[ecol + 1]; bv.z = bh[ecol + 2]; bv.w = bh[ecol + 3];

    #pragma unroll
    for (int i = 0; i < 8; i++) {
        float4 v;
        v.x = acc[i][0] + bv.x;
        v.y = acc[i][1] + bv.y;
        v.z = acc[i][2] + bv.z;
        v.w = acc[i][3] + bv.w;
        *(float4*)(g_hy + (size_t)(rr0 + m0 + i) * Dn + ecol) = v;
    }
}

// ---------------------------------------------------------------------------
// Kernel 4: out[b,n,e] = hy[seg[n], b, e]   (float4 gather, hy L2-hot)
// ---------------------------------------------------------------------------
__global__ void gather_k(float4* __restrict__ out)
{
    const int idx = blockIdx.x * 256 + threadIdx.x;   // < B*N*128
    const int e4 = idx & 127;
    const int nb = idx >> 7;            // b*N + n
    const int n  = nb & (Nn - 1);
    const int b  = nb >> 16;
    const int s  = g_seg[n];
    out[idx] = ((const float4*)g_hy)[((s * Bn + b) << 7) + e4];
}

// ---------------------------------------------------------------------------
extern "C" void kernel_launch(void* const* d_in, const int* in_sizes, int n_in,
                              void* d_out, int out_size)
{
    const float* x   = (const float*)d_in[0];
    const int*   ixw = (const int*)d_in[1];
    const float* Wf  = (const float*)d_in[2];
    const float* bf  = (const float*)d_in[3];
    const float* Wg  = (const float*)d_in[4];
    const float* bg  = (const float*)d_in[5];
    const float* Wh  = (const float*)d_in[6];
    const float* bh  = (const float*)d_in[7];

    // 0) seg ids
    detect_k<<<1, 32>>>(ixw);
    cvt_k<<<Nn / 256, 256>>>(ixw);

    // 1) zero accumulators
    zero_k<<<(Sn * Bn * Dn / 4) / 256, 256>>>();

    // 2) fused g/f tf32 tensor GEMM + exp + segment atomic accumulation
    main_k<<<dim3(Dn / BE, (Bn * Nn) / BM), 256>>>(x, Wf, bf, Wg, bg);

    // 3) y = ynum/denom
    div_k<<<(Sn * Bn * Dn / 4) / 256, 256>>>();

    // 4) hy = y @ Wh^T + bh   (4096 x 512 x 512)
    hy_k<<<dim3(Dn / BE, (Sn * Bn) / BM), 256>>>(Wh, bh);

    // 5) out = gather(hy, seg)
    gather_k<<<(Bn * Nn * 128) / 256, 256>>>((float4*)d_out);

    (void)in_sizes; (void)n_in; (void)out_size;
}

// round 12
// speedup vs baseline: 3.6419x; 2.5838x over previous
#include <cuda_runtime.h>
#include <cstdint>

// Problem constants (fixed shapes for SoftAgg_8873402434226)
#define Bn 8
#define Nn 65536
#define Dn 512
#define Sn 512

// Scratch (sanctioned: __device__ globals)
__device__ float g_denom[Sn * Bn * Dn];
__device__ float g_ynum[Sn * Bn * Dn];
__device__ float g_hy[Sn * Bn * Dn];
__device__ int   g_seg[Nn];
__device__ int   g_is64;
__device__ float g_xt[(size_t)Bn * Nn * Dn];   // x pre-converted to tf32
__device__ float g_wgt[Dn * Dn];               // Wg tf32
__device__ float g_wft[Dn * Dn];               // Wf tf32

// ---------------------------------------------------------------------------
__device__ __forceinline__ uint32_t smem_u32(const void* p) {
    uint32_t a;
    asm("{ .reg .u64 t; cvta.to.shared.u64 t, %1; cvt.u32.u64 %0, t; }" : "=r"(a) : "l"(p));
    return a;
}

__device__ __forceinline__ float f2tf32(float f) {
    unsigned o;
    asm("cvt.rna.tf32.f32 %0, %1;" : "=r"(o) : "f"(f));
    return __uint_as_float(o);
}

__device__ __forceinline__ void mma_tf32(float* c, const unsigned* a, const unsigned* b) {
    asm volatile(
        "mma.sync.aligned.m16n8k8.row.col.f32.tf32.tf32.f32 "
        "{%0,%1,%2,%3}, {%4,%5,%6,%7}, {%8,%9}, {%0,%1,%2,%3};"
        : "+f"(c[0]), "+f"(c[1]), "+f"(c[2]), "+f"(c[3])
        : "r"(a[0]), "r"(a[1]), "r"(a[2]), "r"(a[3]), "r"(b[0]), "r"(b[1]));
}

#define CP_ASYNC16(dst, src) \
    asm volatile("cp.async.cg.shared.global [%0], [%1], 16;" :: "r"(dst), "l"(src))
#define CP_COMMIT() asm volatile("cp.async.commit_group;" ::: "memory")
#define CP_WAIT1()  asm volatile("cp.async.wait_group 1;" ::: "memory")

// ---------------------------------------------------------------------------
__global__ void detect_k(const int* __restrict__ ixw) {
    if (threadIdx.x == 0 && blockIdx.x == 0) {
        int z = 1;
        for (int i = 1; i < 128; i += 2)
            if (ixw[i] != 0) { z = 0; break; }
        g_is64 = z;
    }
}

__global__ void cvt_k(const int* __restrict__ ixw) {
    const int n = blockIdx.x * blockDim.x + threadIdx.x;
    int v = g_is64 ? ixw[2 * n] : ixw[n];
    g_seg[n] = v & (Sn - 1);
}

__global__ void zero_k() {
    int i = blockIdx.x * blockDim.x + threadIdx.x;
    float4 z = make_float4(0.f, 0.f, 0.f, 0.f);
    ((float4*)g_denom)[i] = z;
    ((float4*)g_ynum)[i]  = z;
}

// x -> tf32 (rna), float4-wide
__global__ void xcvt_k(const float4* __restrict__ x) {
    size_t i = (size_t)blockIdx.x * 256 + threadIdx.x;
    float4 v = x[i];
    v.x = f2tf32(v.x); v.y = f2tf32(v.y); v.z = f2tf32(v.z); v.w = f2tf32(v.w);
    ((float4*)g_xt)[i] = v;
}

// Wg/Wf -> tf32
__global__ void wcvt_k(const float4* __restrict__ Wg, const float4* __restrict__ Wf) {
    int i = blockIdx.x * 256 + threadIdx.x;
    float4 g = Wg[i];
    g.x = f2tf32(g.x); g.y = f2tf32(g.y); g.z = f2tf32(g.z); g.w = f2tf32(g.w);
    ((float4*)g_wgt)[i] = g;
    float4 f = Wf[i];
    f.x = f2tf32(f.x); f.y = f2tf32(f.y); f.z = f2tf32(f.z); f.w = f2tf32(f.w);
    ((float4*)g_wft)[i] = f;
}

// ---------------------------------------------------------------------------
// main_k: fused dual tf32 GEMM (mma.sync) + exp + segment atomic accumulation.
// CTA tile 128m x 128e, 8 warps = 2(m) x 4(e), warp tile 64m x 32e x {g,f}.
// Smem: A[m][k] stride 36, B[e][k] stride 36 (g rows 0..127, f rows 128..255)
//   -> staging (cp.async 16B) AND fragment LDS both bank-conflict-free.
// 2-stage cp.async pipeline over k-chunks of 32.
// ---------------------------------------------------------------------------
#define KC 32
#define AKS 36                          // row stride in floats
#define A_F (128 * AKS)                 // 4608 floats
#define B_F (256 * AKS)                 // 9216 floats
#define STAGE_F (A_F + B_F)             // 13824 floats = 55296 B
#define SMEM_TOTAL (2 * STAGE_F * 4)    // 110592 B

__global__ __launch_bounds__(256, 1)
void main_k(const float* __restrict__ bfv, const float* __restrict__ bgv)
{
    extern __shared__ float sm[];
    const uint32_t sb = smem_u32(sm);

    const int tid  = threadIdx.x;
    const int lane = tid & 31;
    const int wid  = tid >> 5;
    const int lr   = lane >> 2, lq = lane & 3;
    const int wm   = wid & 1;            // m half (64 rows)
    const int we   = wid >> 1;           // e quarter (32 cols)

    const int eb    = blockIdx.x * 128;  // e base
    const int row0  = blockIdx.y * 128;  // flattened row (b*N + n)
    const int b     = row0 >> 16;
    const int nbase = row0 & (Nn - 1);

    // staging coords
    const int ar = tid >> 3, ac = tid & 7;   // A: 4 chunks via +32 rows
    // B: 8 chunks via +32 rows

    float cg[4][4][4], cf[4][4][4];
    #pragma unroll
    for (int mt = 0; mt < 4; mt++)
        #pragma unroll
        for (int nt = 0; nt < 4; nt++)
            #pragma unroll
            for (int r = 0; r < 4; r++) { cg[mt][nt][r] = 0.f; cf[mt][nt][r] = 0.f; }

    // stage loader: k-chunk kc into buffer bs
    auto stage = [&](int kc, int bs) {
        const uint32_t base = sb + (uint32_t)bs * STAGE_F * 4;
        // A: 128 rows x 32 k
        const float* asrc = g_xt + (size_t)(row0 + ar) * Dn + kc * KC + ac * 4;
        #pragma unroll
        for (int it = 0; it < 4; it++) {
            uint32_t dst = base + ((ar + it * 32) * AKS + ac * 4) * 4;
            CP_ASYNC16(dst, asrc + (size_t)(it * 32) * Dn);
        }
        // B: 256 rows (g then f) x 32 k
        #pragma unroll
        for (int it = 0; it < 8; it++) {
            int n = ar + it * 32;
            const float* src = (n < 128)
                ? g_wgt + (size_t)(eb + n) * Dn + kc * KC + ac * 4
                : g_wft + (size_t)(eb + n - 128) * Dn + kc * KC + ac * 4;
            uint32_t dst = base + (A_F + n * AKS + ac * 4) * 4;
            CP_ASYNC16(dst, src);
        }
    };

    stage(0, 0);
    CP_COMMIT();

    for (int kc = 0; kc < Dn / KC; kc++) {
        if (kc + 1 < Dn / KC) stage(kc + 1, (kc + 1) & 1);
        CP_COMMIT();
        CP_WAIT1();
        __syncthreads();

        const float* Ab = sm + (kc & 1) * STAGE_F;
        const float* Bb = Ab + A_F;

        #pragma unroll
        for (int k8 = 0; k8 < KC / 8; k8++) {
            const int k0 = k8 * 8;
            unsigned a[4][4];
            #pragma unroll
            for (int mt = 0; mt < 4; mt++) {
                const float* ap = Ab + (wm * 64 + mt * 16 + lr) * AKS + k0 + lq;
                a[mt][0] = __float_as_uint(ap[0]);
                a[mt][1] = __float_as_uint(ap[8 * AKS]);
                a[mt][2] = __float_as_uint(ap[4]);
                a[mt][3] = __float_as_uint(ap[8 * AKS + 4]);
            }
            unsigned bg_[4][2], bf_[4][2];
            #pragma unroll
            for (int nt = 0; nt < 4; nt++) {
                const float* gp = Bb + (we * 32 + nt * 8 + lr) * AKS + k0 + lq;
                bg_[nt][0] = __float_as_uint(gp[0]);
                bg_[nt][1] = __float_as_uint(gp[4]);
                const float* fp = gp + 128 * AKS;
                bf_[nt][0] = __float_as_uint(fp[0]);
                bf_[nt][1] = __float_as_uint(fp[4]);
            }
            #pragma unroll
            for (int mt = 0; mt < 4; mt++)
                #pragma unroll
                for (int nt = 0; nt < 4; nt++) {
                    mma_tf32(cg[mt][nt], a[mt], bg_[nt]);
                    mma_tf32(cf[mt][nt], a[mt], bf_[nt]);
                }
        }
        __syncthreads();
    }

    // epilogue: bias, exp, atomic scatter
    float biasg[4][2], biasf[4][2];
    #pragma unroll
    for (int nt = 0; nt < 4; nt++)
        #pragma unroll
        for (int cc = 0; cc < 2; cc++) {
            const int col = eb + we * 32 + nt * 8 + 2 * lq + cc;
            biasg[nt][cc] = bgv[col];
            biasf[nt][cc] = bfv[col];
        }

    #pragma unroll
    for (int mt = 0; mt < 4; mt++) {
        #pragma unroll
        for (int h = 0; h < 2; h++) {
            const int seg = g_seg[nbase + wm * 64 + mt * 16 + h * 8 + lr];
            const int base = ((seg * Bn + b) << 9) + eb + we * 32 + 2 * lq;
            #pragma unroll
            for (int nt = 0; nt < 4; nt++) {
                #pragma unroll
                for (int cc = 0; cc < 2; cc++) {
                    const int o = base + nt * 8 + cc;
                    float ev = __expf(cg[mt][nt][h * 2 + cc] + biasg[nt][cc]);
                    atomicAdd(&g_denom[o], ev);
                    atomicAdd(&g_ynum[o], (cf[mt][nt][h * 2 + cc] + biasf[nt][cc]) * ev);
                }
            }
        }
    }
}

// ---------------------------------------------------------------------------
// div, hy (fp32 SIMT), gather — unchanged from R9
// ---------------------------------------------------------------------------
__global__ void div_k() {
    int i = blockIdx.x * blockDim.x + threadIdx.x;
    float4 d = ((const float4*)g_denom)[i];
    float4 a = ((const float4*)g_ynum)[i];
    float4 r;
    r.x = (d.x > 0.f) ? a.x / d.x : 0.f;
    r.y = (d.y > 0.f) ? a.y / d.y : 0.f;
    r.z = (d.z > 0.f) ? a.z / d.z : 0.f;
    r.w = (d.w > 0.f) ? a.w / d.w : 0.f;
    ((float4*)g_ynum)[i] = r;
}

#define HASTR 132
#define HBSTR 68

__global__ __launch_bounds__(256, 2)
void hy_k(const float* __restrict__ Wh, const float* __restrict__ bh)
{
    __shared__ float As[16 * HASTR];
    __shared__ float Bh[16 * HBSTR];

    const int tid = threadIdx.x;
    const int ec  = blockIdx.x;
    const int rr0 = blockIdx.y * 128;
    const int e0  = ec * 64;

    const int tx = tid & 15, ty = tid >> 4;
    const int m0 = ty * 8;
    const int srow = tid & 127, sh = tid >> 7;
    const int we = tid >> 2, wc = tid & 3;

    float acc[8][4];
    #pragma unroll
    for (int i = 0; i < 8; i++)
        #pragma unroll
        for (int j = 0; j < 4; j++) acc[i][j] = 0.f;

    const float4* y4  = (const float4*)g_ynum;
    const float4* wh4 = (const float4*)Wh;

    for (int kc = 0; kc < Dn; kc += 16) {
        const int kq = kc >> 2;
        #pragma unroll
        for (int it = 0; it < 2; it++) {
            int cc = sh * 2 + it;
            float4 v = y4[(size_t)(rr0 + srow) * 128 + kq + cc];
            As[(cc * 4 + 0) * HASTR + srow] = v.x;
            As[(cc * 4 + 1) * HASTR + srow] = v.y;
            As[(cc * 4 + 2) * HASTR + srow] = v.z;
            As[(cc * 4 + 3) * HASTR + srow] = v.w;
        }
        {
            float4 hv = wh4[(size_t)(e0 + we) * 128 + kq + wc];
            Bh[(wc * 4 + 0) * HBSTR + we] = hv.x;
            Bh[(wc * 4 + 1) * HBSTR + we] = hv.y;
            Bh[(wc * 4 + 2) * HBSTR + we] = hv.z;
            Bh[(wc * 4 + 3) * HBSTR + we] = hv.w;
        }
        __syncthreads();

        #pragma unroll
        for (int k = 0; k < 16; k++) {
            float4 a0 = *(const float4*)(As + k * HASTR + m0);
            float4 a1 = *(const float4*)(As + k * HASTR + m0 + 4);
            float4 bv = *(const float4*)(Bh + k * HBSTR + tx * 4);
            float a[8] = {a0.x, a0.y, a0.z, a0.w, a1.x, a1.y, a1.z, a1.w};
            float hv[4] = {bv.x, bv.y, bv.z, bv.w};
            #pragma unroll
            for (int i = 0; i < 8; i++)
                #pragma unroll
                for (int j = 0; j < 4; j++)
                    acc[i][j] += a[i] * hv[j];
        }
        __syncthreads();
    }

    const int ecol = e0 + tx * 4;
    float4 bv;
    bv.x = bh[ecol]; bv.y = bh[ecol + 1]; bv.z = bh[ecol + 2]; bv.w = bh[ecol + 3];
    #pragma unroll
    for (int i = 0; i < 8; i++) {
        float4 v;
        v.x = acc[i][0] + bv.x;
        v.y = acc[i][1] + bv.y;
        v.z = acc[i][2] + bv.z;
        v.w = acc[i][3] + bv.w;
        *(float4*)(g_hy + (size_t)(rr0 + m0 + i) * Dn + ecol) = v;
    }
}

__global__ void gather_k(float4* __restrict__ out)
{
    const int idx = blockIdx.x * 256 + threadIdx.x;
    const int e4 = idx & 127;
    const int nb = idx >> 7;
    const int n  = nb & (Nn - 1);
    const int b  = nb >> 16;
    const int s  = g_seg[n];
    out[idx] = ((const float4*)g_hy)[((s * Bn + b) << 7) + e4];
}

// ---------------------------------------------------------------------------
extern "C" void kernel_launch(void* const* d_in, const int* in_sizes, int n_in,
                              void* d_out, int out_size)
{
    const float* x   = (const float*)d_in[0];
    const int*   ixw = (const int*)d_in[1];
    const float* Wf  = (const float*)d_in[2];
    const float* bf  = (const float*)d_in[3];
    const float* Wg  = (const float*)d_in[4];
    const float* bg  = (const float*)d_in[5];
    const float* Wh  = (const float*)d_in[6];
    const float* bh  = (const float*)d_in[7];

    cudaFuncSetAttribute(main_k, cudaFuncAttributeMaxDynamicSharedMemorySize, SMEM_TOTAL);

    // 0) seg ids + tf32 pre-conversion
    detect_k<<<1, 32>>>(ixw);
    cvt_k<<<Nn / 256, 256>>>(ixw);
    xcvt_k<<<(int)(((size_t)Bn * Nn * Dn / 4) / 256), 256>>>((const float4*)x);
    wcvt_k<<<(Dn * Dn / 4) / 256, 256>>>((const float4*)Wg, (const float4*)Wf);

    // 1) zero accumulators
    zero_k<<<(Sn * Bn * Dn / 4) / 256, 256>>>();

    // 2) fused dual tf32 GEMM + exp + segment atomic accumulation
    main_k<<<dim3(4, (Bn * Nn) / 128), 256, SMEM_TOTAL>>>(bf, bg);

    // 3) y = ynum/denom
    div_k<<<(Sn * Bn * Dn / 4) / 256, 256>>>();

    // 4) hy = y @ Wh^T + bh
    hy_k<<<dim3(8, (Sn * Bn) / 128), 256>>>(Wh, bh);

    // 5) out = gather(hy, seg)
    gather_k<<<(Bn * Nn * 128) / 256, 256>>>((float4*)d_out);

    (void)in_sizes; (void)n_in; (void)out_size;
}